// round 10
// baseline (speedup 1.0000x reference)
#include <cuda_runtime.h>
#include <cuda_fp16.h>

#define NN    50000
#define NE    800000
#define ETOT  (NE + NN)       // edges + self loops
#define FOUT  256             // HEADS * HIDDEN
#define HID   64
#define NPAD  50176           // 196 * 256
#define NBLK  196

// ---------------- scratch (device globals; no allocation allowed) ----------
__device__ __half g_hh[NN * FOUT];     // per-layer node features, fp16 [N, H*C]
__device__ float  g_asrc[NN * 4];
__device__ float  g_adst[NN * 4];
__device__ float  g_ew[ETOT * 4];      // per-edge exp(leaky(logit)) (4 heads)
__device__ float  g_feat1[NN * HID];
__device__ float  g_feat2[NN * HID];

// CSR build (dst-sorted edges; built once per call, reused by both layers)
// g_cnt starts zero (static init) and is re-zeroed by k_scan23 each call.
__device__ int g_cnt[NPAD];
__device__ int g_incl[NPAD];
__device__ int g_bsum[NBLK];
__device__ int g_row[NN + 1];
__device__ int g_cur[NN];
__device__ int g_es[ETOT];             // src node ids grouped by dst

// ---------------- CSR build ------------------------------------------------
__global__ void k_count(const int* __restrict__ ei) {
    int e = blockIdx.x * blockDim.x + threadIdx.x;
    if (e >= ETOT) return;
    int dst = (e < NE) ? ei[NE + e] : (e - NE);
    atomicAdd(&g_cnt[dst], 1);
}

__global__ void k_scan1() {
    __shared__ int s[256];
    int t = threadIdx.x, i = blockIdx.x * 256 + t;
    int c = g_cnt[i];
    s[t] = c;
    __syncthreads();
#pragma unroll
    for (int off = 1; off < 256; off <<= 1) {
        int v = (t >= off) ? s[t - off] : 0;
        __syncthreads();
        s[t] += v;
        __syncthreads();
    }
    g_incl[i] = s[t];
    if (t == 255) g_bsum[blockIdx.x] = s[255];
}

// merged scan2+scan3: each block computes its own prefix offset from g_bsum,
// then finalizes row/cur for its 256 nodes and re-zeroes g_cnt.
__global__ void k_scan23() {
    __shared__ int s[256];
    int t = threadIdx.x;
    int b = blockIdx.x;
    s[t] = (t < b) ? g_bsum[t] : 0;    // sum of block-sums before block b
    __syncthreads();
#pragma unroll
    for (int off = 128; off > 0; off >>= 1) {
        if (t < off) s[t] += s[t + off];
        __syncthreads();
    }
    int boff = s[0];
    int i = b * 256 + t;
    int inc = g_incl[i] + boff;
    int c = g_cnt[i];
    if (i < NN) {
        g_row[i + 1] = inc;
        g_cur[i] = inc - c;
    }
    g_cnt[i] = 0;                      // ready for next call (replay-invariant)
    if (i == 0) g_row[0] = 0;
}

__global__ void k_scatter(const int* __restrict__ ei) {
    int e = blockIdx.x * blockDim.x + threadIdx.x;
    if (e >= ETOT) return;
    int src, dst;
    if (e < NE) { src = ei[e]; dst = ei[NE + e]; }
    else        { src = dst = e - NE; }
    int pos = atomicAdd(&g_cur[dst], 1);
    g_es[pos] = src;
}

// ---------------- feature GEMM: g_hh = fp16(X @ W)  (W: [FIN, 256]) -------
template <int FIN>
__global__ void k_gemm(const float* __restrict__ X, const float* __restrict__ W) {
    extern __shared__ float sm[];
    float* Wsh = sm;                 // [FIN][256]
    float* Xs  = sm + FIN * FOUT;    // [FIN][8]
    int t = threadIdx.x;

    for (int i = t; i < FIN * (FOUT / 4); i += 256)
        ((float4*)Wsh)[i] = ((const float4*)W)[i];

    const int nTiles = (NN + 7) / 8;
    for (int tile = blockIdx.x; tile < nTiles; tile += gridDim.x) {
        int n0 = tile * 8;
        __syncthreads();
        for (int idx = t; idx < 8 * FIN; idx += 256) {
            int k = idx >> 3, i = idx & 7;
            int n = n0 + i;
            Xs[idx] = (n < NN) ? X[n * FIN + k] : 0.f;
        }
        __syncthreads();

        float acc[8];
#pragma unroll
        for (int i = 0; i < 8; i++) acc[i] = 0.f;
#pragma unroll
        for (int k = 0; k < FIN; k++) {
            float  w  = Wsh[k * FOUT + t];
            float4 xa = *(const float4*)&Xs[k * 8];
            float4 xb = *(const float4*)&Xs[k * 8 + 4];
            acc[0] = fmaf(xa.x, w, acc[0]);
            acc[1] = fmaf(xa.y, w, acc[1]);
            acc[2] = fmaf(xa.z, w, acc[2]);
            acc[3] = fmaf(xa.w, w, acc[3]);
            acc[4] = fmaf(xb.x, w, acc[4]);
            acc[5] = fmaf(xb.y, w, acc[5]);
            acc[6] = fmaf(xb.z, w, acc[6]);
            acc[7] = fmaf(xb.w, w, acc[7]);
        }
#pragma unroll
        for (int i = 0; i < 8; i++) {
            int n = n0 + i;
            if (n < NN) g_hh[n * FOUT + t] = __float2half_rn(acc[i]);
        }
    }
}

// ---------------- alpha_src / alpha_dst per (node, head) ------------------
__global__ void k_alpha(const float* __restrict__ a_src, const float* __restrict__ a_dst) {
    int i = blockIdx.x * blockDim.x + threadIdx.x;
    if (i >= NN * 4) return;
    int node = i >> 2, hd = i & 3;
    const __half2* hp = (const __half2*)&g_hh[node * FOUT + hd * HID];
    const float2*  ap = (const float2*)&a_src[hd * HID];
    const float2*  dp = (const float2*)&a_dst[hd * HID];
    float s = 0.f, d = 0.f;
#pragma unroll
    for (int j = 0; j < HID / 2; j++) {
        float2 h2 = __half22float2(hp[j]);
        float2 a2 = ap[j], d2 = dp[j];
        s += h2.x * a2.x + h2.y * a2.y;
        d += h2.x * d2.x + h2.y * d2.y;
    }
    g_asrc[i] = s;
    g_adst[i] = d;
}

// ---------------- fused softmax-aggregate + normalize + mean + ELU --------
// 4 warps per node (quad); block = 2 quads = 2 nodes; named barrier per quad.
// pass 1 stores w = exp(leaky(e)) directly (no max; logits bounded, validated)
__device__ __forceinline__ void acc_edge(float w, uint4 u,
                                         float4& a0, float4& a1) {
    float2 f;
    f = __half22float2(*(__half2*)&u.x); a0.x = fmaf(w, f.x, a0.x); a0.y = fmaf(w, f.y, a0.y);
    f = __half22float2(*(__half2*)&u.y); a0.z = fmaf(w, f.x, a0.z); a0.w = fmaf(w, f.y, a0.w);
    f = __half22float2(*(__half2*)&u.z); a1.x = fmaf(w, f.x, a1.x); a1.y = fmaf(w, f.y, a1.y);
    f = __half22float2(*(__half2*)&u.w); a1.z = fmaf(w, f.x, a1.z); a1.w = fmaf(w, f.y, a1.w);
}

__global__ void __launch_bounds__(256) k_agg(const float* __restrict__ bias,
                                             float* __restrict__ outf) {
    __shared__ float red[2][3][32][9];   // [quad][warp 1..3][lane][a0,a1,wsum]

    int t    = threadIdx.x;
    int warp = t >> 5;          // 0..7
    int quad = warp >> 2;       // 0..1
    int wq   = warp & 3;        // warp within quad
    int lane = t & 31;
    int qtid = t & 127;         // thread within quad
    int head = lane >> 3;

    int n = blockIdx.x * 2 + quad;      // grid exactly NN/2 -> always valid
    int beg = g_row[n], end = g_row[n + 1];
    float4 ad4 = *(const float4*)&g_adst[n * 4];

    // pass 1: per-edge exp(leaky(logit)) -> g_ew (striped over 128 threads)
    for (int i = beg + qtid; i < end; i += 128) {
        int s = g_es[i];
        float4 as = *(const float4*)&g_asrc[s * 4];
        float e0 = as.x + ad4.x; e0 = (e0 >= 0.f) ? e0 : 0.2f * e0;
        float e1 = as.y + ad4.y; e1 = (e1 >= 0.f) ? e1 : 0.2f * e1;
        float e2 = as.z + ad4.z; e2 = (e2 >= 0.f) ? e2 : 0.2f * e2;
        float e3 = as.w + ad4.w; e3 = (e3 >= 0.f) ? e3 : 0.2f * e3;
        *(float4*)&g_ew[i * 4] =
            make_float4(__expf(e0), __expf(e1), __expf(e2), __expf(e3));
    }
    __threadfence_block();
    asm volatile("bar.sync %0, %1;" :: "r"(quad + 1), "r"(128) : "memory");

    // pass 2: each warp takes a contiguous quarter of the edge range;
    // unroll-2 with prefetched indices (R8-validated inner loop)
    int deg = end - beg;
    int qlen = (deg + 3) >> 2;
    int mb = beg + wq * qlen;
    int me = mb + qlen; if (me > end) me = end; if (mb > end) mb = end;

    float4 a0 = {0.f, 0.f, 0.f, 0.f}, a1 = {0.f, 0.f, 0.f, 0.f};
    float wsum = 0.f;
    const uint4* h16 = (const uint4*)g_hh;   // 8 halves per uint4; 32 per row
    int i = mb;
    int sA = 0, sB = 0;
    if (i + 2 <= me) { sA = g_es[i]; sB = g_es[i + 1]; }
    while (i + 2 <= me) {
        float w0 = g_ew[i * 4 + head];
        float w1 = g_ew[i * 4 + 4 + head];
        uint4 u0 = h16[(size_t)sA * 32 + lane];
        uint4 u1 = h16[(size_t)sB * 32 + lane];
        int j = i + 2;
        if (j + 2 <= me) { sA = g_es[j]; sB = g_es[j + 1]; }
        wsum += w0 + w1;
        acc_edge(w0, u0, a0, a1);
        acc_edge(w1, u1, a0, a1);
        i = j;
    }
    if (i < me) {
        int s0 = g_es[i];
        float w0 = g_ew[i * 4 + head];
        uint4 u0 = h16[(size_t)s0 * 32 + lane];
        wsum += w0;
        acc_edge(w0, u0, a0, a1);
    }

    // combine the 4 warps' partials (warps 1-3 -> smem, warp 0 reduces)
    if (wq > 0) {
        float* p = &red[quad][wq - 1][lane][0];
        p[0] = a0.x; p[1] = a0.y; p[2] = a0.z; p[3] = a0.w;
        p[4] = a1.x; p[5] = a1.y; p[6] = a1.z; p[7] = a1.w;
        p[8] = wsum;
    }
    asm volatile("bar.sync %0, %1;" :: "r"(quad + 1), "r"(128) : "memory");
    if (wq != 0) return;

#pragma unroll
    for (int w = 0; w < 3; w++) {
        const float* p = &red[quad][w][lane][0];
        a0.x += p[0]; a0.y += p[1]; a0.z += p[2]; a0.w += p[3];
        a1.x += p[4]; a1.y += p[5]; a1.z += p[6]; a1.w += p[7];
        wsum += p[8];
    }

    float nrm = 1.f / wsum;
    a0.x *= nrm; a0.y *= nrm; a0.z *= nrm; a0.w *= nrm;
    a1.x *= nrm; a1.y *= nrm; a1.z *= nrm; a1.w *= nrm;

    // head sum across lanes {L, L^8, L^16, L^24} (head bits are lane bits 3,4)
#pragma unroll
    for (int o = 8; o <= 16; o <<= 1) {
        a0.x += __shfl_xor_sync(0xffffffffu, a0.x, o);
        a0.y += __shfl_xor_sync(0xffffffffu, a0.y, o);
        a0.z += __shfl_xor_sync(0xffffffffu, a0.z, o);
        a0.w += __shfl_xor_sync(0xffffffffu, a0.w, o);
        a1.x += __shfl_xor_sync(0xffffffffu, a1.x, o);
        a1.y += __shfl_xor_sync(0xffffffffu, a1.y, o);
        a1.z += __shfl_xor_sync(0xffffffffu, a1.z, o);
        a1.w += __shfl_xor_sync(0xffffffffu, a1.w, o);
    }

    if (lane < 8) {
        float4 b0 = *(const float4*)&bias[lane * 8];
        float4 b1 = *(const float4*)&bias[lane * 8 + 4];
        float v;
        float4 o0, o1;
        v = 0.25f * a0.x + b0.x; o0.x = (v > 0.f) ? v : (__expf(v) - 1.f);
        v = 0.25f * a0.y + b0.y; o0.y = (v > 0.f) ? v : (__expf(v) - 1.f);
        v = 0.25f * a0.z + b0.z; o0.z = (v > 0.f) ? v : (__expf(v) - 1.f);
        v = 0.25f * a0.w + b0.w; o0.w = (v > 0.f) ? v : (__expf(v) - 1.f);
        v = 0.25f * a1.x + b1.x; o1.x = (v > 0.f) ? v : (__expf(v) - 1.f);
        v = 0.25f * a1.y + b1.y; o1.y = (v > 0.f) ? v : (__expf(v) - 1.f);
        v = 0.25f * a1.z + b1.z; o1.z = (v > 0.f) ? v : (__expf(v) - 1.f);
        v = 0.25f * a1.w + b1.w; o1.w = (v > 0.f) ? v : (__expf(v) - 1.f);
        float4* op = (float4*)&outf[n * HID + lane * 8];
        op[0] = o0;
        op[1] = o1;
    }
}

// ---------------- scorer MLP: warp per node -------------------------------
__global__ void k_scorer(const float* __restrict__ feat, const float* __restrict__ donor,
                         const float* __restrict__ Ws1, const float* __restrict__ bs1,
                         const float* __restrict__ Ws2, const float* __restrict__ bs2,
                         float* __restrict__ out) {
    __shared__ float sW1[96 * 64];
    __shared__ float sW2[64];
    __shared__ float sB[64];
    __shared__ float sD[32];
    int t = threadIdx.x;
    for (int i = t; i < 96 * 64; i += 256) sW1[i] = Ws1[i];
    if (t < 64) { sW2[t] = Ws2[t]; sB[t] = bs1[t]; }
    if (t < 32) sD[t] = donor[t];
    __syncthreads();

    int warp = t >> 5, lane = t & 31;
    float b2v = bs2[0];
    for (int n = blockIdx.x * 8 + warp; n < NN; n += gridDim.x * 8) {
        float f0 = feat[n * 64 + lane];
        float f1 = feat[n * 64 + 32 + lane];
        float h0 = 0.f, h1 = 0.f;
#pragma unroll
        for (int k = 0; k < 32; k++) {
            float xk = __shfl_sync(0xffffffffu, f0, k);
            h0 = fmaf(xk, sW1[k * 64 + lane], h0);
            h1 = fmaf(xk, sW1[k * 64 + 32 + lane], h1);
        }
#pragma unroll
        for (int k = 0; k < 32; k++) {
            float xk = __shfl_sync(0xffffffffu, f1, k);
            h0 = fmaf(xk, sW1[(k + 32) * 64 + lane], h0);
            h1 = fmaf(xk, sW1[(k + 32) * 64 + 32 + lane], h1);
        }
#pragma unroll
        for (int k = 0; k < 32; k++) {
            float xk = sD[k];
            h0 = fmaf(xk, sW1[(k + 64) * 64 + lane], h0);
            h1 = fmaf(xk, sW1[(k + 64) * 64 + 32 + lane], h1);
        }
        h0 = fmaxf(h0 + sB[lane], 0.f);
        h1 = fmaxf(h1 + sB[lane + 32], 0.f);
        float p = h0 * sW2[lane] + h1 * sW2[lane + 32];
#pragma unroll
        for (int o = 16; o > 0; o >>= 1) p += __shfl_xor_sync(0xffffffffu, p, o);
        if (lane == 0) out[n] = p + b2v;
    }
}

// ---------------- launch ---------------------------------------------------
extern "C" void kernel_launch(void* const* d_in, const int* in_sizes, int n_in,
                              void* d_out, int out_size) {
    const float* x     = (const float*)d_in[0];
    const int*   ei    = (const int*)  d_in[1];
    const float* donor = (const float*)d_in[2];
    const float* W1    = (const float*)d_in[3];
    const float* as1   = (const float*)d_in[4];
    const float* ad1   = (const float*)d_in[5];
    const float* b1    = (const float*)d_in[6];
    const float* W2    = (const float*)d_in[7];
    const float* as2   = (const float*)d_in[8];
    const float* ad2   = (const float*)d_in[9];
    const float* b2    = (const float*)d_in[10];
    const float* Ws1   = (const float*)d_in[11];
    const float* bs1   = (const float*)d_in[12];
    const float* Ws2   = (const float*)d_in[13];
    const float* bs2   = (const float*)d_in[14];
    float* out = (float*)d_out;

    float *feat1, *feat2;
    cudaGetSymbolAddress((void**)&feat1, g_feat1);
    cudaGetSymbolAddress((void**)&feat2, g_feat2);

    const int smem27 = 27 * FOUT * 4 + 8 * 27 * 4;
    const int smem64 = 64 * FOUT * 4 + 8 * 64 * 4;
    cudaFuncSetAttribute(k_gemm<27>, cudaFuncAttributeMaxDynamicSharedMemorySize, smem27);
    cudaFuncSetAttribute(k_gemm<64>, cudaFuncAttributeMaxDynamicSharedMemorySize, smem64);

    const int alphaGrid = (NN * 4 + 255) / 256;
    const int edgeGrid  = (ETOT + 255) / 256;
    const int aggGrid   = NN / 2;                // 2 nodes per block (NN even)

    // ---- CSR build (g_cnt zero on entry: static init / re-zeroed in scan23) ----
    k_count<<<edgeGrid, 256>>>(ei);
    k_scan1<<<NBLK, 256>>>();
    k_scan23<<<NBLK, 256>>>();
    k_scatter<<<edgeGrid, 256>>>(ei);

    // ---- layer 1 ----
    k_gemm<27><<<1036, 256, smem27>>>(x, W1);
    k_alpha<<<alphaGrid, 256>>>(as1, ad1);
    k_agg<<<aggGrid, 256>>>(b1, feat1);

    // ---- layer 2 ----
    k_gemm<64><<<444, 256, smem64>>>(feat1, W2);
    k_alpha<<<alphaGrid, 256>>>(as2, ad2);
    k_agg<<<aggGrid, 256>>>(b2, feat2);

    // ---- scorer ----
    k_scorer<<<1184, 256>>>(feat2, donor, Ws1, bs1, Ws2, bs2, out);
}

// round 11
// speedup vs baseline: 1.3755x; 1.3755x over previous
#include <cuda_runtime.h>
#include <cuda_fp16.h>

#define NN    50000
#define NE    800000
#define ETOT  (NE + NN)       // edges + self loops
#define FOUT  256             // HEADS * HIDDEN
#define HID   64
#define NPAD  50176           // 196 * 256
#define NBLK  196

// ---------------- scratch (device globals; no allocation allowed) ----------
__device__ __half g_hh[NN * FOUT];     // per-layer node features, fp16 [N, H*C]
__device__ float  g_asrc[NN * 4];
__device__ float  g_adst[NN * 4];
__device__ float  g_feat1[NN * HID];
__device__ float  g_feat2[NN * HID];

// CSR build (dst-sorted edges; built once per call, reused by both layers)
// g_cnt starts zero (static init) and is re-zeroed by k_scan23 each call.
__device__ int g_cnt[NPAD];
__device__ int g_incl[NPAD];
__device__ int g_bsum[NBLK];
__device__ int g_row[NN + 1];
__device__ int g_cur[NN];
__device__ int g_es[ETOT];             // src node ids grouped by dst

// ---------------- CSR build ------------------------------------------------
__global__ void k_count(const int* __restrict__ ei) {
    int e = blockIdx.x * blockDim.x + threadIdx.x;
    if (e >= ETOT) return;
    int dst = (e < NE) ? ei[NE + e] : (e - NE);
    atomicAdd(&g_cnt[dst], 1);
}

__global__ void k_scan1() {
    __shared__ int s[256];
    int t = threadIdx.x, i = blockIdx.x * 256 + t;
    int c = g_cnt[i];
    s[t] = c;
    __syncthreads();
#pragma unroll
    for (int off = 1; off < 256; off <<= 1) {
        int v = (t >= off) ? s[t - off] : 0;
        __syncthreads();
        s[t] += v;
        __syncthreads();
    }
    g_incl[i] = s[t];
    if (t == 255) g_bsum[blockIdx.x] = s[255];
}

// merged scan2+scan3: each block computes its own prefix offset from g_bsum,
// then finalizes row/cur for its 256 nodes and re-zeroes g_cnt.
__global__ void k_scan23() {
    __shared__ int s[256];
    int t = threadIdx.x;
    int b = blockIdx.x;
    s[t] = (t < b) ? g_bsum[t] : 0;    // sum of block-sums before block b
    __syncthreads();
#pragma unroll
    for (int off = 128; off > 0; off >>= 1) {
        if (t < off) s[t] += s[t + off];
        __syncthreads();
    }
    int boff = s[0];
    int i = b * 256 + t;
    int inc = g_incl[i] + boff;
    int c = g_cnt[i];
    if (i < NN) {
        g_row[i + 1] = inc;
        g_cur[i] = inc - c;
    }
    g_cnt[i] = 0;                      // ready for next call (replay-invariant)
    if (i == 0) g_row[0] = 0;
}

__global__ void k_scatter(const int* __restrict__ ei) {
    int e = blockIdx.x * blockDim.x + threadIdx.x;
    if (e >= ETOT) return;
    int src, dst;
    if (e < NE) { src = ei[e]; dst = ei[NE + e]; }
    else        { src = dst = e - NE; }
    int pos = atomicAdd(&g_cur[dst], 1);
    g_es[pos] = src;
}

// ---------------- feature GEMM: g_hh = fp16(X @ W)  (W: [FIN, 256]) -------
template <int FIN>
__global__ void k_gemm(const float* __restrict__ X, const float* __restrict__ W) {
    extern __shared__ float sm[];
    float* Wsh = sm;                 // [FIN][256]
    float* Xs  = sm + FIN * FOUT;    // [FIN][8]
    int t = threadIdx.x;

    for (int i = t; i < FIN * (FOUT / 4); i += 256)
        ((float4*)Wsh)[i] = ((const float4*)W)[i];

    const int nTiles = (NN + 7) / 8;
    for (int tile = blockIdx.x; tile < nTiles; tile += gridDim.x) {
        int n0 = tile * 8;
        __syncthreads();
        for (int idx = t; idx < 8 * FIN; idx += 256) {
            int k = idx >> 3, i = idx & 7;
            int n = n0 + i;
            Xs[idx] = (n < NN) ? X[n * FIN + k] : 0.f;
        }
        __syncthreads();

        float acc[8];
#pragma unroll
        for (int i = 0; i < 8; i++) acc[i] = 0.f;
#pragma unroll
        for (int k = 0; k < FIN; k++) {
            float  w  = Wsh[k * FOUT + t];
            float4 xa = *(const float4*)&Xs[k * 8];
            float4 xb = *(const float4*)&Xs[k * 8 + 4];
            acc[0] = fmaf(xa.x, w, acc[0]);
            acc[1] = fmaf(xa.y, w, acc[1]);
            acc[2] = fmaf(xa.z, w, acc[2]);
            acc[3] = fmaf(xa.w, w, acc[3]);
            acc[4] = fmaf(xb.x, w, acc[4]);
            acc[5] = fmaf(xb.y, w, acc[5]);
            acc[6] = fmaf(xb.z, w, acc[6]);
            acc[7] = fmaf(xb.w, w, acc[7]);
        }
#pragma unroll
        for (int i = 0; i < 8; i++) {
            int n = n0 + i;
            if (n < NN) g_hh[n * FOUT + t] = __float2half_rn(acc[i]);
        }
    }
}

// ---------------- alpha_src / alpha_dst per (node, head) ------------------
__global__ void k_alpha(const float* __restrict__ a_src, const float* __restrict__ a_dst) {
    int i = blockIdx.x * blockDim.x + threadIdx.x;
    if (i >= NN * 4) return;
    int node = i >> 2, hd = i & 3;
    const __half2* hp = (const __half2*)&g_hh[node * FOUT + hd * HID];
    const float2*  ap = (const float2*)&a_src[hd * HID];
    const float2*  dp = (const float2*)&a_dst[hd * HID];
    float s = 0.f, d = 0.f;
#pragma unroll
    for (int j = 0; j < HID / 2; j++) {
        float2 h2 = __half22float2(hp[j]);
        float2 a2 = ap[j], d2 = dp[j];
        s += h2.x * a2.x + h2.y * a2.y;
        d += h2.x * d2.x + h2.y * d2.y;
    }
    g_asrc[i] = s;
    g_adst[i] = d;
}

// ---------------- fused single-pass softmax-aggregate + mean + ELU --------
// one warp per destination node; edges contiguous in g_es[row[n]..row[n+1])
// w = exp(leaky(logit)) computed inline (no max; logits bounded, validated);
// edge index AND its asrc value prefetched one iteration ahead (unroll-2).
__device__ __forceinline__ void acc_edge(float w, uint4 u,
                                         float4& a0, float4& a1) {
    float2 f;
    f = __half22float2(*(__half2*)&u.x); a0.x = fmaf(w, f.x, a0.x); a0.y = fmaf(w, f.y, a0.y);
    f = __half22float2(*(__half2*)&u.y); a0.z = fmaf(w, f.x, a0.z); a0.w = fmaf(w, f.y, a0.w);
    f = __half22float2(*(__half2*)&u.z); a1.x = fmaf(w, f.x, a1.x); a1.y = fmaf(w, f.y, a1.y);
    f = __half22float2(*(__half2*)&u.w); a1.z = fmaf(w, f.x, a1.z); a1.w = fmaf(w, f.y, a1.w);
}

__global__ void __launch_bounds__(256) k_agg(const float* __restrict__ bias,
                                             float* __restrict__ outf) {
    int gw = (blockIdx.x * blockDim.x + threadIdx.x) >> 5;
    int lane = threadIdx.x & 31;
    if (gw >= NN) return;
    int n = gw;
    int beg = g_row[n], end = g_row[n + 1];
    int head = lane >> 3;
    float adh = __ldg(&g_adst[n * 4 + head]);

    float4 a0 = {0.f, 0.f, 0.f, 0.f}, a1 = {0.f, 0.f, 0.f, 0.f};
    float wsum = 0.f;
    const uint4* h16 = (const uint4*)g_hh;   // 8 halves per uint4; 32 per row
    int i = beg;
    int sA = 0, sB = 0;
    float aA = 0.f, aB = 0.f;
    if (i + 2 <= end) {
        sA = g_es[i]; sB = g_es[i + 1];
        aA = __ldg(&g_asrc[sA * 4 + head]);
        aB = __ldg(&g_asrc[sB * 4 + head]);
    }
    while (i + 2 <= end) {
        uint4 u0 = h16[(size_t)sA * 32 + lane];
        uint4 u1 = h16[(size_t)sB * 32 + lane];
        float e0 = aA + adh; e0 = (e0 >= 0.f) ? e0 : 0.2f * e0;
        float e1 = aB + adh; e1 = (e1 >= 0.f) ? e1 : 0.2f * e1;
        float w0 = __expf(e0);
        float w1 = __expf(e1);
        int j = i + 2;
        if (j + 2 <= end) {
            sA = g_es[j]; sB = g_es[j + 1];
            aA = __ldg(&g_asrc[sA * 4 + head]);
            aB = __ldg(&g_asrc[sB * 4 + head]);
        }
        wsum += w0 + w1;
        acc_edge(w0, u0, a0, a1);
        acc_edge(w1, u1, a0, a1);
        i = j;
    }
    if (i < end) {
        int s0 = g_es[i];
        float e0 = __ldg(&g_asrc[s0 * 4 + head]) + adh;
        e0 = (e0 >= 0.f) ? e0 : 0.2f * e0;
        float w0 = __expf(e0);
        uint4 u0 = h16[(size_t)s0 * 32 + lane];
        wsum += w0;
        acc_edge(w0, u0, a0, a1);
    }

    float nrm = 1.f / wsum;
    a0.x *= nrm; a0.y *= nrm; a0.z *= nrm; a0.w *= nrm;
    a1.x *= nrm; a1.y *= nrm; a1.z *= nrm; a1.w *= nrm;

    // head sum across lanes {L, L^8, L^16, L^24} (head bits are lane bits 3,4)
#pragma unroll
    for (int o = 8; o <= 16; o <<= 1) {
        a0.x += __shfl_xor_sync(0xffffffffu, a0.x, o);
        a0.y += __shfl_xor_sync(0xffffffffu, a0.y, o);
        a0.z += __shfl_xor_sync(0xffffffffu, a0.z, o);
        a0.w += __shfl_xor_sync(0xffffffffu, a0.w, o);
        a1.x += __shfl_xor_sync(0xffffffffu, a1.x, o);
        a1.y += __shfl_xor_sync(0xffffffffu, a1.y, o);
        a1.z += __shfl_xor_sync(0xffffffffu, a1.z, o);
        a1.w += __shfl_xor_sync(0xffffffffu, a1.w, o);
    }

    if (lane < 8) {
        float4 b0 = *(const float4*)&bias[lane * 8];
        float4 b1 = *(const float4*)&bias[lane * 8 + 4];
        float v;
        float4 o0, o1;
        v = 0.25f * a0.x + b0.x; o0.x = (v > 0.f) ? v : (__expf(v) - 1.f);
        v = 0.25f * a0.y + b0.y; o0.y = (v > 0.f) ? v : (__expf(v) - 1.f);
        v = 0.25f * a0.z + b0.z; o0.z = (v > 0.f) ? v : (__expf(v) - 1.f);
        v = 0.25f * a0.w + b0.w; o0.w = (v > 0.f) ? v : (__expf(v) - 1.f);
        v = 0.25f * a1.x + b1.x; o1.x = (v > 0.f) ? v : (__expf(v) - 1.f);
        v = 0.25f * a1.y + b1.y; o1.y = (v > 0.f) ? v : (__expf(v) - 1.f);
        v = 0.25f * a1.z + b1.z; o1.z = (v > 0.f) ? v : (__expf(v) - 1.f);
        v = 0.25f * a1.w + b1.w; o1.w = (v > 0.f) ? v : (__expf(v) - 1.f);
        float4* op = (float4*)&outf[n * HID + lane * 8];
        op[0] = o0;
        op[1] = o1;
    }
}

// ---------------- scorer MLP: warp per node -------------------------------
__global__ void k_scorer(const float* __restrict__ feat, const float* __restrict__ donor,
                         const float* __restrict__ Ws1, const float* __restrict__ bs1,
                         const float* __restrict__ Ws2, const float* __restrict__ bs2,
                         float* __restrict__ out) {
    __shared__ float sW1[96 * 64];
    __shared__ float sW2[64];
    __shared__ float sB[64];
    __shared__ float sD[32];
    int t = threadIdx.x;
    for (int i = t; i < 96 * 64; i += 256) sW1[i] = Ws1[i];
    if (t < 64) { sW2[t] = Ws2[t]; sB[t] = bs1[t]; }
    if (t < 32) sD[t] = donor[t];
    __syncthreads();

    int warp = t >> 5, lane = t & 31;
    float b2v = bs2[0];
    for (int n = blockIdx.x * 8 + warp; n < NN; n += gridDim.x * 8) {
        float f0 = feat[n * 64 + lane];
        float f1 = feat[n * 64 + 32 + lane];
        float h0 = 0.f, h1 = 0.f;
#pragma unroll
        for (int k = 0; k < 32; k++) {
            float xk = __shfl_sync(0xffffffffu, f0, k);
            h0 = fmaf(xk, sW1[k * 64 + lane], h0);
            h1 = fmaf(xk, sW1[k * 64 + 32 + lane], h1);
        }
#pragma unroll
        for (int k = 0; k < 32; k++) {
            float xk = __shfl_sync(0xffffffffu, f1, k);
            h0 = fmaf(xk, sW1[(k + 32) * 64 + lane], h0);
            h1 = fmaf(xk, sW1[(k + 32) * 64 + 32 + lane], h1);
        }
#pragma unroll
        for (int k = 0; k < 32; k++) {
            float xk = sD[k];
            h0 = fmaf(xk, sW1[(k + 64) * 64 + lane], h0);
            h1 = fmaf(xk, sW1[(k + 64) * 64 + 32 + lane], h1);
        }
        h0 = fmaxf(h0 + sB[lane], 0.f);
        h1 = fmaxf(h1 + sB[lane + 32], 0.f);
        float p = h0 * sW2[lane] + h1 * sW2[lane + 32];
#pragma unroll
        for (int o = 16; o > 0; o >>= 1) p += __shfl_xor_sync(0xffffffffu, p, o);
        if (lane == 0) out[n] = p + b2v;
    }
}

// ---------------- launch ---------------------------------------------------
extern "C" void kernel_launch(void* const* d_in, const int* in_sizes, int n_in,
                              void* d_out, int out_size) {
    const float* x     = (const float*)d_in[0];
    const int*   ei    = (const int*)  d_in[1];
    const float* donor = (const float*)d_in[2];
    const float* W1    = (const float*)d_in[3];
    const float* as1   = (const float*)d_in[4];
    const float* ad1   = (const float*)d_in[5];
    const float* b1    = (const float*)d_in[6];
    const float* W2    = (const float*)d_in[7];
    const float* as2   = (const float*)d_in[8];
    const float* ad2   = (const float*)d_in[9];
    const float* b2    = (const float*)d_in[10];
    const float* Ws1   = (const float*)d_in[11];
    const float* bs1   = (const float*)d_in[12];
    const float* Ws2   = (const float*)d_in[13];
    const float* bs2   = (const float*)d_in[14];
    float* out = (float*)d_out;

    float *feat1, *feat2;
    cudaGetSymbolAddress((void**)&feat1, g_feat1);
    cudaGetSymbolAddress((void**)&feat2, g_feat2);

    const int smem27 = 27 * FOUT * 4 + 8 * 27 * 4;
    const int smem64 = 64 * FOUT * 4 + 8 * 64 * 4;
    cudaFuncSetAttribute(k_gemm<27>, cudaFuncAttributeMaxDynamicSharedMemorySize, smem27);
    cudaFuncSetAttribute(k_gemm<64>, cudaFuncAttributeMaxDynamicSharedMemorySize, smem64);

    const int alphaGrid = (NN * 4 + 255) / 256;
    const int edgeGrid  = (ETOT + 255) / 256;
    const int aggGrid   = (NN + 7) / 8;          // warp per node, 8 warps/block

    // ---- CSR build (g_cnt zero on entry: static init / re-zeroed in scan23) ----
    k_count<<<edgeGrid, 256>>>(ei);
    k_scan1<<<NBLK, 256>>>();
    k_scan23<<<NBLK, 256>>>();
    k_scatter<<<edgeGrid, 256>>>(ei);

    // ---- layer 1 ----
    k_gemm<27><<<1036, 256, smem27>>>(x, W1);
    k_alpha<<<alphaGrid, 256>>>(as1, ad1);
    k_agg<<<aggGrid, 256>>>(b1, feat1);

    // ---- layer 2 ----
    k_gemm<64><<<444, 256, smem64>>>(feat1, W2);
    k_alpha<<<alphaGrid, 256>>>(as2, ad2);
    k_agg<<<aggGrid, 256>>>(b2, feat2);

    // ---- scorer ----
    k_scorer<<<1184, 256>>>(feat2, donor, Ws1, bs1, Ws2, bs2, out);
}

// round 12
// speedup vs baseline: 1.3767x; 1.0009x over previous
#include <cuda_runtime.h>
#include <cuda_fp16.h>

#define NN    50000
#define NE    800000
#define ETOT  (NE + NN)       // edges + self loops
#define FOUT  256             // HEADS * HIDDEN
#define HID   64
#define NPAD  50176           // 196 * 256
#define NBLK  196

// ---------------- scratch (device globals; no allocation allowed) ----------
__device__ __half g_hh[NN * FOUT];     // per-layer node features, fp16 [N, H*C]
__device__ float  g_asrc[NN * 4];
__device__ float  g_adst[NN * 4];
__device__ float  g_feat1[NN * HID];
__device__ float  g_feat2[NN * HID];

// CSR build (dst-sorted edges; built once per call, reused by both layers)
// g_cnt starts zero (static init) and is re-zeroed by k_scan23 each call.
__device__ int g_cnt[NPAD];
__device__ int g_incl[NPAD];
__device__ int g_bsum[NBLK];
__device__ int g_row[NN + 1];
__device__ int g_cur[NN];
__device__ int g_es[ETOT];             // src node ids grouped by dst

// ---------------- CSR build ------------------------------------------------
__global__ void k_count(const int* __restrict__ ei) {
    int e = blockIdx.x * blockDim.x + threadIdx.x;
    if (e >= ETOT) return;
    int dst = (e < NE) ? ei[NE + e] : (e - NE);
    atomicAdd(&g_cnt[dst], 1);
}

__global__ void k_scan1() {
    __shared__ int s[256];
    int t = threadIdx.x, i = blockIdx.x * 256 + t;
    int c = g_cnt[i];
    s[t] = c;
    __syncthreads();
#pragma unroll
    for (int off = 1; off < 256; off <<= 1) {
        int v = (t >= off) ? s[t - off] : 0;
        __syncthreads();
        s[t] += v;
        __syncthreads();
    }
    g_incl[i] = s[t];
    if (t == 255) g_bsum[blockIdx.x] = s[255];
}

// merged scan2+scan3: each block computes its own prefix offset from g_bsum,
// then finalizes row/cur for its 256 nodes and re-zeroes g_cnt.
__global__ void k_scan23() {
    __shared__ int s[256];
    int t = threadIdx.x;
    int b = blockIdx.x;
    s[t] = (t < b) ? g_bsum[t] : 0;    // sum of block-sums before block b
    __syncthreads();
#pragma unroll
    for (int off = 128; off > 0; off >>= 1) {
        if (t < off) s[t] += s[t + off];
        __syncthreads();
    }
    int boff = s[0];
    int i = b * 256 + t;
    int inc = g_incl[i] + boff;
    int c = g_cnt[i];
    if (i < NN) {
        g_row[i + 1] = inc;
        g_cur[i] = inc - c;
    }
    g_cnt[i] = 0;                      // ready for next call (replay-invariant)
    if (i == 0) g_row[0] = 0;
}

__global__ void k_scatter(const int* __restrict__ ei) {
    int e = blockIdx.x * blockDim.x + threadIdx.x;
    if (e >= ETOT) return;
    int src, dst;
    if (e < NE) { src = ei[e]; dst = ei[NE + e]; }
    else        { src = dst = e - NE; }
    int pos = atomicAdd(&g_cur[dst], 1);
    g_es[pos] = src;
}

// ---------------- feature GEMM: g_hh = fp16(X @ W)  (W: [FIN, 256]) -------
template <int FIN>
__global__ void k_gemm(const float* __restrict__ X, const float* __restrict__ W) {
    extern __shared__ float sm[];
    float* Wsh = sm;                 // [FIN][256]
    float* Xs  = sm + FIN * FOUT;    // [FIN][8]
    int t = threadIdx.x;

    for (int i = t; i < FIN * (FOUT / 4); i += 256)
        ((float4*)Wsh)[i] = ((const float4*)W)[i];

    const int nTiles = (NN + 7) / 8;
    for (int tile = blockIdx.x; tile < nTiles; tile += gridDim.x) {
        int n0 = tile * 8;
        __syncthreads();
        for (int idx = t; idx < 8 * FIN; idx += 256) {
            int k = idx >> 3, i = idx & 7;
            int n = n0 + i;
            Xs[idx] = (n < NN) ? X[n * FIN + k] : 0.f;
        }
        __syncthreads();

        float acc[8];
#pragma unroll
        for (int i = 0; i < 8; i++) acc[i] = 0.f;
#pragma unroll
        for (int k = 0; k < FIN; k++) {
            float  w  = Wsh[k * FOUT + t];
            float4 xa = *(const float4*)&Xs[k * 8];
            float4 xb = *(const float4*)&Xs[k * 8 + 4];
            acc[0] = fmaf(xa.x, w, acc[0]);
            acc[1] = fmaf(xa.y, w, acc[1]);
            acc[2] = fmaf(xa.z, w, acc[2]);
            acc[3] = fmaf(xa.w, w, acc[3]);
            acc[4] = fmaf(xb.x, w, acc[4]);
            acc[5] = fmaf(xb.y, w, acc[5]);
            acc[6] = fmaf(xb.z, w, acc[6]);
            acc[7] = fmaf(xb.w, w, acc[7]);
        }
#pragma unroll
        for (int i = 0; i < 8; i++) {
            int n = n0 + i;
            if (n < NN) g_hh[n * FOUT + t] = __float2half_rn(acc[i]);
        }
    }
}

// ---------------- alpha_src / alpha_dst per (node, head) ------------------
__global__ void k_alpha(const float* __restrict__ a_src, const float* __restrict__ a_dst) {
    int i = blockIdx.x * blockDim.x + threadIdx.x;
    if (i >= NN * 4) return;
    int node = i >> 2, hd = i & 3;
    const __half2* hp = (const __half2*)&g_hh[node * FOUT + hd * HID];
    const float2*  ap = (const float2*)&a_src[hd * HID];
    const float2*  dp = (const float2*)&a_dst[hd * HID];
    float s = 0.f, d = 0.f;
#pragma unroll
    for (int j = 0; j < HID / 2; j++) {
        float2 h2 = __half22float2(hp[j]);
        float2 a2 = ap[j], d2 = dp[j];
        s += h2.x * a2.x + h2.y * a2.y;
        d += h2.x * d2.x + h2.y * d2.y;
    }
    g_asrc[i] = s;
    g_adst[i] = d;
}

// ---------------- fused single-pass softmax-aggregate + mean + ELU --------
// one warp per destination node; edges contiguous in g_es[row[n]..row[n+1])
// w = exp(leaky(logit)) computed inline (no max; logits bounded, validated);
// edge index AND its asrc value prefetched one iteration ahead (unroll-2).
__device__ __forceinline__ void acc_edge(float w, uint4 u,
                                         float4& a0, float4& a1) {
    float2 f;
    f = __half22float2(*(__half2*)&u.x); a0.x = fmaf(w, f.x, a0.x); a0.y = fmaf(w, f.y, a0.y);
    f = __half22float2(*(__half2*)&u.y); a0.z = fmaf(w, f.x, a0.z); a0.w = fmaf(w, f.y, a0.w);
    f = __half22float2(*(__half2*)&u.z); a1.x = fmaf(w, f.x, a1.x); a1.y = fmaf(w, f.y, a1.y);
    f = __half22float2(*(__half2*)&u.w); a1.z = fmaf(w, f.x, a1.z); a1.w = fmaf(w, f.y, a1.w);
}

__global__ void __launch_bounds__(256) k_agg(const float* __restrict__ bias,
                                             float* __restrict__ outf) {
    int gw = (blockIdx.x * blockDim.x + threadIdx.x) >> 5;
    int lane = threadIdx.x & 31;
    if (gw >= NN) return;
    int n = gw;
    int beg = g_row[n], end = g_row[n + 1];
    int head = lane >> 3;
    float adh = __ldg(&g_adst[n * 4 + head]);

    float4 a0 = {0.f, 0.f, 0.f, 0.f}, a1 = {0.f, 0.f, 0.f, 0.f};
    float wsum = 0.f;
    const uint4* h16 = (const uint4*)g_hh;   // 8 halves per uint4; 32 per row
    int i = beg;
    int sA = 0, sB = 0;
    float aA = 0.f, aB = 0.f;
    if (i + 2 <= end) {
        sA = g_es[i]; sB = g_es[i + 1];
        aA = __ldg(&g_asrc[sA * 4 + head]);
        aB = __ldg(&g_asrc[sB * 4 + head]);
    }
    while (i + 2 <= end) {
        uint4 u0 = h16[(size_t)sA * 32 + lane];
        uint4 u1 = h16[(size_t)sB * 32 + lane];
        float e0 = aA + adh; e0 = (e0 >= 0.f) ? e0 : 0.2f * e0;
        float e1 = aB + adh; e1 = (e1 >= 0.f) ? e1 : 0.2f * e1;
        float w0 = __expf(e0);
        float w1 = __expf(e1);
        int j = i + 2;
        if (j + 2 <= end) {
            sA = g_es[j]; sB = g_es[j + 1];
            aA = __ldg(&g_asrc[sA * 4 + head]);
            aB = __ldg(&g_asrc[sB * 4 + head]);
        }
        wsum += w0 + w1;
        acc_edge(w0, u0, a0, a1);
        acc_edge(w1, u1, a0, a1);
        i = j;
    }
    if (i < end) {
        int s0 = g_es[i];
        float e0 = __ldg(&g_asrc[s0 * 4 + head]) + adh;
        e0 = (e0 >= 0.f) ? e0 : 0.2f * e0;
        float w0 = __expf(e0);
        uint4 u0 = h16[(size_t)s0 * 32 + lane];
        wsum += w0;
        acc_edge(w0, u0, a0, a1);
    }

    float nrm = 1.f / wsum;
    a0.x *= nrm; a0.y *= nrm; a0.z *= nrm; a0.w *= nrm;
    a1.x *= nrm; a1.y *= nrm; a1.z *= nrm; a1.w *= nrm;

    // head sum across lanes {L, L^8, L^16, L^24} (head bits are lane bits 3,4)
#pragma unroll
    for (int o = 8; o <= 16; o <<= 1) {
        a0.x += __shfl_xor_sync(0xffffffffu, a0.x, o);
        a0.y += __shfl_xor_sync(0xffffffffu, a0.y, o);
        a0.z += __shfl_xor_sync(0xffffffffu, a0.z, o);
        a0.w += __shfl_xor_sync(0xffffffffu, a0.w, o);
        a1.x += __shfl_xor_sync(0xffffffffu, a1.x, o);
        a1.y += __shfl_xor_sync(0xffffffffu, a1.y, o);
        a1.z += __shfl_xor_sync(0xffffffffu, a1.z, o);
        a1.w += __shfl_xor_sync(0xffffffffu, a1.w, o);
    }

    if (lane < 8) {
        float4 b0 = *(const float4*)&bias[lane * 8];
        float4 b1 = *(const float4*)&bias[lane * 8 + 4];
        float v;
        float4 o0, o1;
        v = 0.25f * a0.x + b0.x; o0.x = (v > 0.f) ? v : (__expf(v) - 1.f);
        v = 0.25f * a0.y + b0.y; o0.y = (v > 0.f) ? v : (__expf(v) - 1.f);
        v = 0.25f * a0.z + b0.z; o0.z = (v > 0.f) ? v : (__expf(v) - 1.f);
        v = 0.25f * a0.w + b0.w; o0.w = (v > 0.f) ? v : (__expf(v) - 1.f);
        v = 0.25f * a1.x + b1.x; o1.x = (v > 0.f) ? v : (__expf(v) - 1.f);
        v = 0.25f * a1.y + b1.y; o1.y = (v > 0.f) ? v : (__expf(v) - 1.f);
        v = 0.25f * a1.z + b1.z; o1.z = (v > 0.f) ? v : (__expf(v) - 1.f);
        v = 0.25f * a1.w + b1.w; o1.w = (v > 0.f) ? v : (__expf(v) - 1.f);
        float4* op = (float4*)&outf[n * HID + lane * 8];
        op[0] = o0;
        op[1] = o1;
    }
}

// ---------------- scorer MLP: warp per node -------------------------------
__global__ void k_scorer(const float* __restrict__ feat, const float* __restrict__ donor,
                         const float* __restrict__ Ws1, const float* __restrict__ bs1,
                         const float* __restrict__ Ws2, const float* __restrict__ bs2,
                         float* __restrict__ out) {
    __shared__ float sW1[96 * 64];
    __shared__ float sW2[64];
    __shared__ float sB[64];
    __shared__ float sD[32];
    int t = threadIdx.x;
    for (int i = t; i < 96 * 64; i += 256) sW1[i] = Ws1[i];
    if (t < 64) { sW2[t] = Ws2[t]; sB[t] = bs1[t]; }
    if (t < 32) sD[t] = donor[t];
    __syncthreads();

    int warp = t >> 5, lane = t & 31;
    float b2v = bs2[0];
    for (int n = blockIdx.x * 8 + warp; n < NN; n += gridDim.x * 8) {
        float f0 = feat[n * 64 + lane];
        float f1 = feat[n * 64 + 32 + lane];
        float h0 = 0.f, h1 = 0.f;
#pragma unroll
        for (int k = 0; k < 32; k++) {
            float xk = __shfl_sync(0xffffffffu, f0, k);
            h0 = fmaf(xk, sW1[k * 64 + lane], h0);
            h1 = fmaf(xk, sW1[k * 64 + 32 + lane], h1);
        }
#pragma unroll
        for (int k = 0; k < 32; k++) {
            float xk = __shfl_sync(0xffffffffu, f1, k);
            h0 = fmaf(xk, sW1[(k + 32) * 64 + lane], h0);
            h1 = fmaf(xk, sW1[(k + 32) * 64 + 32 + lane], h1);
        }
#pragma unroll
        for (int k = 0; k < 32; k++) {
            float xk = sD[k];
            h0 = fmaf(xk, sW1[(k + 64) * 64 + lane], h0);
            h1 = fmaf(xk, sW1[(k + 64) * 64 + 32 + lane], h1);
        }
        h0 = fmaxf(h0 + sB[lane], 0.f);
        h1 = fmaxf(h1 + sB[lane + 32], 0.f);
        float p = h0 * sW2[lane] + h1 * sW2[lane + 32];
#pragma unroll
        for (int o = 16; o > 0; o >>= 1) p += __shfl_xor_sync(0xffffffffu, p, o);
        if (lane == 0) out[n] = p + b2v;
    }
}

// ---------------- launch (forked-stream capture: CSR || layer-1 gemm) -----
extern "C" void kernel_launch(void* const* d_in, const int* in_sizes, int n_in,
                              void* d_out, int out_size) {
    const float* x     = (const float*)d_in[0];
    const int*   ei    = (const int*)  d_in[1];
    const float* donor = (const float*)d_in[2];
    const float* W1    = (const float*)d_in[3];
    const float* as1   = (const float*)d_in[4];
    const float* ad1   = (const float*)d_in[5];
    const float* b1    = (const float*)d_in[6];
    const float* W2    = (const float*)d_in[7];
    const float* as2   = (const float*)d_in[8];
    const float* ad2   = (const float*)d_in[9];
    const float* b2    = (const float*)d_in[10];
    const float* Ws1   = (const float*)d_in[11];
    const float* bs1   = (const float*)d_in[12];
    const float* Ws2   = (const float*)d_in[13];
    const float* bs2   = (const float*)d_in[14];
    float* out = (float*)d_out;

    float *feat1, *feat2;
    cudaGetSymbolAddress((void**)&feat1, g_feat1);
    cudaGetSymbolAddress((void**)&feat2, g_feat2);

    const int smem27 = 27 * FOUT * 4 + 8 * 27 * 4;
    const int smem64 = 64 * FOUT * 4 + 8 * 64 * 4;
    cudaFuncSetAttribute(k_gemm<27>, cudaFuncAttributeMaxDynamicSharedMemorySize, smem27);
    cudaFuncSetAttribute(k_gemm<64>, cudaFuncAttributeMaxDynamicSharedMemorySize, smem64);

    const int alphaGrid = (NN * 4 + 255) / 256;
    const int edgeGrid  = (ETOT + 255) / 256;
    const int aggGrid   = (NN + 7) / 8;          // warp per node, 8 warps/block

    // fork a side stream for the CSR build (independent of layer-1 GEMM)
    cudaStream_t sCSR;
    cudaEvent_t evFork, evJoin;
    cudaStreamCreateWithFlags(&sCSR, cudaStreamNonBlocking);
    cudaEventCreateWithFlags(&evFork, cudaEventDisableTiming);
    cudaEventCreateWithFlags(&evJoin, cudaEventDisableTiming);

    cudaEventRecord(evFork, 0);
    cudaStreamWaitEvent(sCSR, evFork, 0);

    // ---- CSR build on side stream ----
    k_count<<<edgeGrid, 256, 0, sCSR>>>(ei);
    k_scan1<<<NBLK, 256, 0, sCSR>>>();
    k_scan23<<<NBLK, 256, 0, sCSR>>>();
    k_scatter<<<edgeGrid, 256, 0, sCSR>>>(ei);
    cudaEventRecord(evJoin, sCSR);

    // ---- layer-1 GEMM + alpha on main stream (parallel with CSR) ----
    k_gemm<27><<<1036, 256, smem27>>>(x, W1);
    k_alpha<<<alphaGrid, 256>>>(as1, ad1);

    // join: agg needs both CSR and alpha
    cudaStreamWaitEvent(0, evJoin, 0);
    k_agg<<<aggGrid, 256>>>(b1, feat1);

    // ---- layer 2 (serial chain) ----
    k_gemm<64><<<444, 256, smem64>>>(feat1, W2);
    k_alpha<<<alphaGrid, 256>>>(as2, ad2);
    k_agg<<<aggGrid, 256>>>(b2, feat2);

    // ---- scorer ----
    k_scorer<<<1184, 256>>>(feat2, donor, Ws1, bs1, Ws2, bs2, out);

    cudaStreamDestroy(sCSR);
    cudaEventDestroy(evFork);
    cudaEventDestroy(evJoin);
}